// round 4
// baseline (speedup 1.0000x reference)
#include <cuda_runtime.h>
#include <cuda_bf16.h>

// out[b,t,v] = sum_d x[b,t,d,v] * w[d] + bias
// x: (B=2, T=512, D=8, V=32000) fp32 ; w: (8,) ; b: (1,)
// HBM-stream kernel v2: 2 output float4 per thread (16 independent LDG.128
// in flight), streaming cache hints (read-once / write-once).

#define BT     1024      // B*T
#define DEPTH  8
#define V      32000
#define V4     (V / 4)   // 8000 float4 per (b,t,d) row
#define HALF   (V4 / 2)  // 4000 — second output element offset

__global__ __launch_bounds__(256) void tokentree_kernel(
    const float4* __restrict__ x,   // (BT, DEPTH, V4)
    const float*  __restrict__ w,   // (DEPTH,)
    const float*  __restrict__ bias,// (1,)
    float4*       __restrict__ out) // (BT, V4)
{
    const int v4 = blockIdx.x * blockDim.x + threadIdx.x;
    if (v4 >= HALF) return;
    const int bt = blockIdx.y;

    // Weights + bias: tiny, L1-resident after first warp.
    float wr[DEPTH];
#pragma unroll
    for (int d = 0; d < DEPTH; d++) wr[d] = __ldg(&w[d]);
    const float b0 = __ldg(&bias[0]);

    const float4* xp = x + (size_t)bt * DEPTH * V4 + v4;

    // 16 independent streaming loads, front-batched -> MLP=16 per thread.
    float4 xa[DEPTH], xb[DEPTH];
#pragma unroll
    for (int d = 0; d < DEPTH; d++) xa[d] = __ldcs(xp + d * V4);
#pragma unroll
    for (int d = 0; d < DEPTH; d++) xb[d] = __ldcs(xp + d * V4 + HALF);

    float4 accA, accB;
    accA.x = b0; accA.y = b0; accA.z = b0; accA.w = b0;
    accB = accA;

#pragma unroll
    for (int d = 0; d < DEPTH; d++) {
        accA.x = fmaf(wr[d], xa[d].x, accA.x);
        accA.y = fmaf(wr[d], xa[d].y, accA.y);
        accA.z = fmaf(wr[d], xa[d].z, accA.z);
        accA.w = fmaf(wr[d], xa[d].w, accA.w);
        accB.x = fmaf(wr[d], xb[d].x, accB.x);
        accB.y = fmaf(wr[d], xb[d].y, accB.y);
        accB.z = fmaf(wr[d], xb[d].z, accB.z);
        accB.w = fmaf(wr[d], xb[d].w, accB.w);
    }

    float4* op = out + (size_t)bt * V4 + v4;
    __stcs(op, accA);
    __stcs(op + HALF, accB);
}

extern "C" void kernel_launch(void* const* d_in, const int* in_sizes, int n_in,
                              void* d_out, int out_size) {
    const float4* x    = (const float4*)d_in[0];
    const float*  w    = (const float*)d_in[1];
    const float*  bias = (const float*)d_in[2];
    float4*       out  = (float4*)d_out;

    dim3 block(256);
    dim3 grid((HALF + 255) / 256, BT);   // (16, 1024)
    tokentree_kernel<<<grid, block>>>(x, w, bias, out);
}